// round 7
// baseline (speedup 1.0000x reference)
#include <cuda_runtime.h>
#include <cstdint>

// B = 16384 samples, D = 2, G = 2500.  Y_surf: [B, 2, 2500] f32 (20KB/row).
// For each b: idx = argmin_g (Ys[b,0,g]-y[b,0])^2 + (Ys[b,1,g]-y[b,1])^2
//             out[b,d] = U_grid[d, idx]
//
// R7: bulk-copy streaming. Each block DMAs whole 20KB rows into smem with
// cp.async.bulk (one op = 160 sequential 128B requests -> max HBM row
// locality), double-buffered via mbarriers. Blocks own CONTIGUOUS sample
// ranges so each block's DRAM stream is one long sequential run. Compute
// (argmin) runs from smem and is ~30x over-provisioned vs the DRAM share.

#define G_CONST 2500
#define ROW_FLOATS (2 * G_CONST)     // 5000 floats
#define ROW_BYTES  (ROW_FLOATS * 4)  // 20000 bytes (mult of 16 -> bulk-ok)
#define G4 625                       // float4 pairs per row half
#define THREADS 256
#define NWARPS (THREADS / 32)
#define GRID_BLOCKS 592              // 4 blocks/SM on 148 SMs, fully resident
#define STAGES 2

#define MBAR_INIT(mb, cnt) \
    asm volatile("mbarrier.init.shared.b64 [%0], %1;" :: "r"(mb), "r"(cnt) : "memory")

#define MBAR_EXPECT_TX(mb, bytes) \
    asm volatile("mbarrier.arrive.expect_tx.shared.b64 _, [%0], %1;" \
                 :: "r"(mb), "r"(bytes) : "memory")

#define BULK_G2S(dst, src, bytes, mb) \
    asm volatile("cp.async.bulk.shared::cta.global.mbarrier::complete_tx::bytes " \
                 "[%0], [%1], %2, [%3];" \
                 :: "r"(dst), "l"(src), "r"(bytes), "r"(mb) : "memory")

#define MBAR_WAIT_PARITY(mb, ph) do {                                         \
    uint32_t _done;                                                           \
    asm volatile("{\n\t.reg .pred p;\n\t"                                     \
        "mbarrier.try_wait.parity.acquire.cta.shared::cta.b64 p, [%1], %2;\n\t" \
        "selp.b32 %0, 1, 0, p;\n\t}"                                          \
        : "=r"(_done) : "r"(mb), "r"(ph) : "memory");                         \
    while (!_done) {                                                          \
        asm volatile("{\n\t.reg .pred p;\n\t"                                 \
            "mbarrier.try_wait.parity.acquire.cta.shared::cta.b64 p, [%1], %2, 0x989680;\n\t" \
            "selp.b32 %0, 1, 0, p;\n\t}"                                      \
            : "=r"(_done) : "r"(mb), "r"(ph) : "memory");                     \
    }                                                                         \
} while (0)

__global__ __launch_bounds__(THREADS)
void lqr_bulk_kernel(const float* __restrict__ y,
                     const float* __restrict__ Y_surf,
                     const float* __restrict__ U_grid,
                     float* __restrict__ out,
                     int B)
{
    __shared__ __align__(16) float buf[STAGES][ROW_FLOATS];   // 2 x 20KB
    __shared__ __align__(8)  unsigned long long mbar[STAGES];
    __shared__ float red_val[NWARPS];
    __shared__ int   red_idx[NWARPS];

    const int tid  = threadIdx.x;
    const int wid  = tid >> 5;
    const int lane = tid & 31;

    // Blocked contiguous partition: block bid owns samples [s0, s0+ns).
    const int base = B / GRID_BLOCKS;
    const int rem  = B % GRID_BLOCKS;
    const int bid  = blockIdx.x;
    const int ns   = base + (bid < rem ? 1 : 0);
    const int s0   = bid * base + (bid < rem ? bid : rem);

    const uint32_t mb0  = (uint32_t)__cvta_generic_to_shared(&mbar[0]);
    const uint32_t mb1  = (uint32_t)__cvta_generic_to_shared(&mbar[1]);
    const uint32_t dst0 = (uint32_t)__cvta_generic_to_shared(&buf[0][0]);
    const uint32_t dst1 = (uint32_t)__cvta_generic_to_shared(&buf[1][0]);

    if (tid == 0) {
        MBAR_INIT(mb0, 1);
        MBAR_INIT(mb1, 1);
    }
    __syncthreads();

    // Prologue: fill both stages.
    if (tid == 0) {
        if (ns > 0) {
            MBAR_EXPECT_TX(mb0, (uint32_t)ROW_BYTES);
            BULK_G2S(dst0, Y_surf + (size_t)s0 * ROW_FLOATS, (uint32_t)ROW_BYTES, mb0);
        }
        if (ns > 1) {
            MBAR_EXPECT_TX(mb1, (uint32_t)ROW_BYTES);
            BULK_G2S(dst1, Y_surf + (size_t)(s0 + 1) * ROW_FLOATS, (uint32_t)ROW_BYTES, mb1);
        }
    }

    for (int n = 0; n < ns; ++n) {
        const int stage = n & 1;
        const uint32_t mb = stage ? mb1 : mb0;
        const int phase = (n >> 1) & 1;      // k-th reuse of this stage
        const int b = s0 + n;

        const float y0 = __ldg(&y[2 * b + 0]);
        const float y1 = __ldg(&y[2 * b + 1]);

        // Wait for this stage's DMA (acquire orders the LDS reads below).
        MBAR_WAIT_PARITY(mb, (uint32_t)phase);

        const float4* __restrict__ f0 =
            reinterpret_cast<const float4*>(&buf[stage][0]);
        const float4* __restrict__ f1 =
            reinterpret_cast<const float4*>(&buf[stage][G_CONST]);  // 10000B off, 16B-aligned

        float best = 3.402823466e38f;
        int   bidx = 0x7fffffff;

        // 625 float4-pairs over 256 threads: k=0,1 guard-free, tail tid<113.
        #pragma unroll
        for (int k = 0; k < 2; ++k) {
            const int i = tid + (k << 8);
            const float4 a = f0[i];
            const float4 c = f1[i];
            const int g = i << 2;
            float dx, dz, d2;
            dx = a.x - y0; dz = c.x - y1; d2 = dx*dx + dz*dz;
            if (d2 < best) { best = d2; bidx = g + 0; }
            dx = a.y - y0; dz = c.y - y1; d2 = dx*dx + dz*dz;
            if (d2 < best) { best = d2; bidx = g + 1; }
            dx = a.z - y0; dz = c.z - y1; d2 = dx*dx + dz*dz;
            if (d2 < best) { best = d2; bidx = g + 2; }
            dx = a.w - y0; dz = c.w - y1; d2 = dx*dx + dz*dz;
            if (d2 < best) { best = d2; bidx = g + 3; }
        }
        {
            const int i = tid + 512;
            if (i < G4) {
                const float4 a = f0[i];
                const float4 c = f1[i];
                const int g = i << 2;
                float dx, dz, d2;
                dx = a.x - y0; dz = c.x - y1; d2 = dx*dx + dz*dz;
                if (d2 < best) { best = d2; bidx = g + 0; }
                dx = a.y - y0; dz = c.y - y1; d2 = dx*dx + dz*dz;
                if (d2 < best) { best = d2; bidx = g + 1; }
                dx = a.z - y0; dz = c.z - y1; d2 = dx*dx + dz*dz;
                if (d2 < best) { best = d2; bidx = g + 2; }
                dx = a.w - y0; dz = c.w - y1; d2 = dx*dx + dz*dz;
                if (d2 < best) { best = d2; bidx = g + 3; }
            }
        }
        // Per-thread indices strictly increase -> '<' keeps first min.

        // Warp argmin with first-index tie-break.
        #pragma unroll
        for (int off = 16; off > 0; off >>= 1) {
            const float ov = __shfl_xor_sync(0xffffffffu, best, off);
            const int   oi = __shfl_xor_sync(0xffffffffu, bidx, off);
            if (ov < best || (ov == best && oi < bidx)) { best = ov; bidx = oi; }
        }
        if (lane == 0) { red_val[wid] = best; red_idx[wid] = bidx; }

        __syncthreads();   // all buf[stage] reads done; reds published

        // Refill this stage for sample n+2 (overlaps with final reduce).
        if (tid == 0 && n + 2 < ns) {
            MBAR_EXPECT_TX(mb, (uint32_t)ROW_BYTES);
            BULK_G2S(stage ? dst1 : dst0,
                     Y_surf + (size_t)(b + 2) * ROW_FLOATS,
                     (uint32_t)ROW_BYTES, mb);
        }

        // Final cross-warp reduce in warp 0.
        if (wid == 0) {
            float v = (lane < NWARPS) ? red_val[lane] : 3.402823466e38f;
            int   ix = (lane < NWARPS) ? red_idx[lane] : 0x7fffffff;
            #pragma unroll
            for (int off = 4; off > 0; off >>= 1) {
                const float ov = __shfl_xor_sync(0xffffffffu, v,  off);
                const int   oi = __shfl_xor_sync(0xffffffffu, ix, off);
                if (ov < v || (ov == v && oi < ix)) { v = ov; ix = oi; }
            }
            if (lane == 0) {
                out[2 * b + 0] = __ldg(&U_grid[ix]);
                out[2 * b + 1] = __ldg(&U_grid[G_CONST + ix]);
            }
        }

        __syncthreads();   // protect red arrays before next sample overwrites
    }
}

extern "C" void kernel_launch(void* const* d_in, const int* in_sizes, int n_in,
                              void* d_out, int out_size)
{
    const float* y      = (const float*)d_in[0];   // [B, 2]
    const float* Y_surf = (const float*)d_in[1];   // [B, 2, 2500]
    const float* U_grid = (const float*)d_in[2];   // [2, 2500]
    float* out = (float*)d_out;                    // [B, 2]

    const int B = in_sizes[0] / 2;

    lqr_bulk_kernel<<<GRID_BLOCKS, THREADS>>>(y, Y_surf, U_grid, out, B);
}

// round 8
// speedup vs baseline: 1.0527x; 1.0527x over previous
#include <cuda_runtime.h>

// B = 16384 samples, D = 2, G = 2500.  Y_surf: [B, 2, 2500] f32.
// For each b: idx = argmin_g (Ys[b,0,g]-y[b,0])^2 + (Ys[b,1,g]-y[b,1])^2
//             out[b,d] = U_grid[d, idx]
//
// R8 = refined R2 (best so far): two interleaved samples per warp, but
//  - guard-free 19-iter main loop (625 = 19*32 + 17), unroll 2 ->
//    8 unconditional front-batched LDG.128 per body (no mid-body branch)
//  - single base pointer: pair rows are contiguous (b1 = b0 + 1), so the
//    4 streams are at float4 offsets {0, 625, 1250, 1875} from one base
//  - 128-thread blocks for finer tail-wave scheduling granularity

#define G_CONST 2500
#define G4 625
#define FULL_ITERS 19            // lane + 32*18 = 607 < 625, all lanes valid
#define WARPS_PER_BLOCK 4

__device__ __forceinline__ void upd(float d2, int g, float& best, int& bidx) {
    // strict '<' keeps FIRST minimum (per-thread indices strictly increase)
    if (d2 < best) { best = d2; bidx = g; }
}

__global__ __launch_bounds__(WARPS_PER_BLOCK * 32)
void lqr_push_kernel8(const float* __restrict__ y,
                      const float* __restrict__ Y_surf,
                      const float* __restrict__ U_grid,
                      float* __restrict__ out,
                      int B)
{
    const int warp = threadIdx.x >> 5;
    const int lane = threadIdx.x & 31;
    const int w    = blockIdx.x * WARPS_PER_BLOCK + warp;

    const int b0 = 2 * w;
    const int b1 = 2 * w + 1;
    if (b0 >= B) return;
    const bool has1 = (b1 < B);

    const float y00 = __ldg(&y[2 * b0 + 0]);
    const float y01 = __ldg(&y[2 * b0 + 1]);
    const float y10 = has1 ? __ldg(&y[2 * b1 + 0]) : 0.0f;
    const float y11 = has1 ? __ldg(&y[2 * b1 + 1]) : 0.0f;

    // Rows b0 and b1 are contiguous: base + {0, 625, 1250, 1875} float4.
    const float4* __restrict__ p0 =
        reinterpret_cast<const float4*>(Y_surf + (size_t)b0 * (size_t)(2 * G_CONST));
    // If B odd and this is the last warp, alias stream 2/3 onto sample 0's
    // rows so loads stay in-bounds (results discarded).
    const int off_c = has1 ? 2 * G4 : 0;      // s1 d0
    const int off_d = has1 ? 3 * G4 : G4;     // s1 d1

    float best0 = 3.402823466e38f, best1 = 3.402823466e38f;
    int   idx0 = 0, idx1 = 0;

    // Guard-free main loop: 19 iterations, every lane in-bounds.
    // unroll 2 -> 8 unconditional LDG.128 per unrolled body.
    #pragma unroll 2
    for (int k = 0; k < FULL_ITERS; ++k) {
        const int i = lane + (k << 5);
        const float4 a  = __ldcs(p0 + i);               // s0 d0
        const float4 c  = __ldcs(p0 + (i + off_c));     // s1 d0
        const float4 bq = __ldcs(p0 + (i + G4));        // s0 d1
        const float4 d  = __ldcs(p0 + (i + off_d));     // s1 d1
        const int g = i << 2;

        float dx, dz;

        dx = a.x - y00; dz = bq.x - y01; upd(dx*dx + dz*dz, g + 0, best0, idx0);
        dx = a.y - y00; dz = bq.y - y01; upd(dx*dx + dz*dz, g + 1, best0, idx0);
        dx = a.z - y00; dz = bq.z - y01; upd(dx*dx + dz*dz, g + 2, best0, idx0);
        dx = a.w - y00; dz = bq.w - y01; upd(dx*dx + dz*dz, g + 3, best0, idx0);

        dx = c.x - y10; dz = d.x - y11; upd(dx*dx + dz*dz, g + 0, best1, idx1);
        dx = c.y - y10; dz = d.y - y11; upd(dx*dx + dz*dz, g + 1, best1, idx1);
        dx = c.z - y10; dz = d.z - y11; upd(dx*dx + dz*dz, g + 2, best1, idx1);
        dx = c.w - y10; dz = d.w - y11; upd(dx*dx + dz*dz, g + 3, best1, idx1);
    }

    // Tail: i = lane + 608, valid for lanes 0..16 only.
    {
        const int i = lane + FULL_ITERS * 32;
        if (i < G4) {
            const float4 a  = __ldcs(p0 + i);
            const float4 c  = __ldcs(p0 + (i + off_c));
            const float4 bq = __ldcs(p0 + (i + G4));
            const float4 d  = __ldcs(p0 + (i + off_d));
            const int g = i << 2;

            float dx, dz;

            dx = a.x - y00; dz = bq.x - y01; upd(dx*dx + dz*dz, g + 0, best0, idx0);
            dx = a.y - y00; dz = bq.y - y01; upd(dx*dx + dz*dz, g + 1, best0, idx0);
            dx = a.z - y00; dz = bq.z - y01; upd(dx*dx + dz*dz, g + 2, best0, idx0);
            dx = a.w - y00; dz = bq.w - y01; upd(dx*dx + dz*dz, g + 3, best0, idx0);

            dx = c.x - y10; dz = d.x - y11; upd(dx*dx + dz*dz, g + 0, best1, idx1);
            dx = c.y - y10; dz = d.y - y11; upd(dx*dx + dz*dz, g + 1, best1, idx1);
            dx = c.z - y10; dz = d.z - y11; upd(dx*dx + dz*dz, g + 2, best1, idx1);
            dx = c.w - y10; dz = d.w - y11; upd(dx*dx + dz*dz, g + 3, best1, idx1);
        }
    }

    // Warp argmin reduction with first-index tie-break, both samples.
    #pragma unroll
    for (int off = 16; off > 0; off >>= 1) {
        const float ov0 = __shfl_xor_sync(0xffffffffu, best0, off);
        const int   oi0 = __shfl_xor_sync(0xffffffffu, idx0,  off);
        if (ov0 < best0 || (ov0 == best0 && oi0 < idx0)) { best0 = ov0; idx0 = oi0; }

        const float ov1 = __shfl_xor_sync(0xffffffffu, best1, off);
        const int   oi1 = __shfl_xor_sync(0xffffffffu, idx1,  off);
        if (ov1 < best1 || (ov1 == best1 && oi1 < idx1)) { best1 = ov1; idx1 = oi1; }
    }

    if (lane == 0) {
        out[2 * b0 + 0] = __ldg(&U_grid[idx0]);
        out[2 * b0 + 1] = __ldg(&U_grid[G_CONST + idx0]);
        if (has1) {
            out[2 * b1 + 0] = __ldg(&U_grid[idx1]);
            out[2 * b1 + 1] = __ldg(&U_grid[G_CONST + idx1]);
        }
    }
}

extern "C" void kernel_launch(void* const* d_in, const int* in_sizes, int n_in,
                              void* d_out, int out_size)
{
    const float* y      = (const float*)d_in[0];   // [B, 2]
    const float* Y_surf = (const float*)d_in[1];   // [B, 2, 2500]
    const float* U_grid = (const float*)d_in[2];   // [2, 2500]
    float* out = (float*)d_out;                    // [B, 2]

    const int B = in_sizes[0] / 2;

    const int threads = WARPS_PER_BLOCK * 32;                     // 128
    const int pairs   = (B + 1) / 2;                              // 2 samples/warp
    const int blocks  = (pairs + WARPS_PER_BLOCK - 1) / WARPS_PER_BLOCK;  // 2048

    lqr_push_kernel8<<<blocks, threads>>>(y, Y_surf, U_grid, out, B);
}

// round 9
// speedup vs baseline: 1.1524x; 1.0946x over previous
#include <cuda_runtime.h>

// B = 16384 samples, D = 2, G = 2500 grid points.
// Y_surf: [B, 2, 2500] f32.  For each b:
//   idx = argmin_g (Ys[b,0,g]-y[b,0])^2 + (Ys[b,1,g]-y[b,1])^2
//   out[b,d] = U_grid[d, idx]
//
// R9 = R2 verbatim (champion reproduction run).
// 2 interleaved samples per warp, 1024 blocks x 256 threads, guarded
// stride-32 loop with unroll 2 -> 8 independent LDG.128 in flight.

#define G_CONST 2500
#define G4_CONST 625            // G/4 (2500 % 4 == 0; rows are 16B-aligned)
#define WARPS_PER_BLOCK 8

__device__ __forceinline__ void upd(float d2, int g, float& best, int& bidx) {
    // strict '<' keeps FIRST minimum (per-thread indices strictly increase)
    if (d2 < best) { best = d2; bidx = g; }
}

__global__ __launch_bounds__(WARPS_PER_BLOCK * 32, 1)
void lqr_push_kernel9(const float* __restrict__ y,
                      const float* __restrict__ Y_surf,
                      const float* __restrict__ U_grid,
                      float* __restrict__ out,
                      int B)
{
    const int warp = threadIdx.x >> 5;
    const int lane = threadIdx.x & 31;
    const int w    = blockIdx.x * WARPS_PER_BLOCK + warp;

    const int b0 = 2 * w;
    const int b1 = 2 * w + 1;
    if (b0 >= B) return;
    const bool has1 = (b1 < B);          // uniform; B is even in practice

    // Per-sample targets.
    const float y00 = __ldg(&y[2 * b0 + 0]);
    const float y01 = __ldg(&y[2 * b0 + 1]);
    const float y10 = has1 ? __ldg(&y[2 * b1 + 0]) : 0.0f;
    const float y11 = has1 ? __ldg(&y[2 * b1 + 1]) : 0.0f;

    const size_t row0 = (size_t)b0 * (size_t)(2 * G_CONST);
    // if !has1, alias to row0 so loads stay in-bounds; results discarded.
    const size_t row1 = has1 ? (size_t)b1 * (size_t)(2 * G_CONST) : row0;

    const float4* __restrict__ pa = reinterpret_cast<const float4*>(Y_surf + row0);            // s0, d0
    const float4* __restrict__ pb = reinterpret_cast<const float4*>(Y_surf + row0 + G_CONST);  // s0, d1
    const float4* __restrict__ pc = reinterpret_cast<const float4*>(Y_surf + row1);            // s1, d0
    const float4* __restrict__ pd = reinterpret_cast<const float4*>(Y_surf + row1 + G_CONST);  // s1, d1

    float best0 = 3.402823466e38f, best1 = 3.402823466e38f;
    int   idx0 = 0, idx1 = 0;

    // 4 independent 16B streaming loads per iteration; unroll 2 -> 8 in flight.
    #pragma unroll 2
    for (int i = lane; i < G4_CONST; i += 32) {
        const float4 a = __ldcs(pa + i);
        const float4 c = __ldcs(pc + i);
        const float4 bq = __ldcs(pb + i);
        const float4 d = __ldcs(pd + i);
        const int g = i << 2;

        float dx, dz;

        dx = a.x - y00; dz = bq.x - y01; upd(dx*dx + dz*dz, g + 0, best0, idx0);
        dx = a.y - y00; dz = bq.y - y01; upd(dx*dx + dz*dz, g + 1, best0, idx0);
        dx = a.z - y00; dz = bq.z - y01; upd(dx*dx + dz*dz, g + 2, best0, idx0);
        dx = a.w - y00; dz = bq.w - y01; upd(dx*dx + dz*dz, g + 3, best0, idx0);

        dx = c.x - y10; dz = d.x - y11; upd(dx*dx + dz*dz, g + 0, best1, idx1);
        dx = c.y - y10; dz = d.y - y11; upd(dx*dx + dz*dz, g + 1, best1, idx1);
        dx = c.z - y10; dz = d.z - y11; upd(dx*dx + dz*dz, g + 2, best1, idx1);
        dx = c.w - y10; dz = d.w - y11; upd(dx*dx + dz*dz, g + 3, best1, idx1);
    }

    // Warp argmin reduction with first-index tie-break, both samples.
    #pragma unroll
    for (int off = 16; off > 0; off >>= 1) {
        const float ov0 = __shfl_xor_sync(0xffffffffu, best0, off);
        const int   oi0 = __shfl_xor_sync(0xffffffffu, idx0,  off);
        if (ov0 < best0 || (ov0 == best0 && oi0 < idx0)) { best0 = ov0; idx0 = oi0; }

        const float ov1 = __shfl_xor_sync(0xffffffffu, best1, off);
        const int   oi1 = __shfl_xor_sync(0xffffffffu, idx1,  off);
        if (ov1 < best1 || (ov1 == best1 && oi1 < idx1)) { best1 = ov1; idx1 = oi1; }
    }

    if (lane == 0) {
        out[2 * b0 + 0] = __ldg(&U_grid[idx0]);
        out[2 * b0 + 1] = __ldg(&U_grid[G_CONST + idx0]);
        if (has1) {
            out[2 * b1 + 0] = __ldg(&U_grid[idx1]);
            out[2 * b1 + 1] = __ldg(&U_grid[G_CONST + idx1]);
        }
    }
}

extern "C" void kernel_launch(void* const* d_in, const int* in_sizes, int n_in,
                              void* d_out, int out_size)
{
    const float* y      = (const float*)d_in[0];   // [B, 2]
    const float* Y_surf = (const float*)d_in[1];   // [B, 2, 2500]
    const float* U_grid = (const float*)d_in[2];   // [2, 2500]
    float* out = (float*)d_out;                    // [B, 2]

    const int B = in_sizes[0] / 2;

    const int threads = WARPS_PER_BLOCK * 32;                     // 256
    const int pairs   = (B + 1) / 2;                              // samples per warp = 2
    const int blocks  = (pairs + WARPS_PER_BLOCK - 1) / WARPS_PER_BLOCK;  // 1024

    lqr_push_kernel9<<<blocks, threads>>>(y, Y_surf, U_grid, out, B);
}